// round 3
// baseline (speedup 1.0000x reference)
#include <cuda_runtime.h>
#include <cstdint>
#include <cstddef>

#define L_SEQ 32768
#define DIM   512
#define DIM4  2048
#define NCTA  32

// Scratch (static device globals: allocation-free per harness rules)
__device__ float g_xp[(size_t)L_SEQ * DIM4];   // 256 MB x-projection
__device__ float g_h[2][DIM];                  // double-buffered hidden state
__device__ int   g_flags[NCTA];                // per-CTA progress

// ---------------------------------------------------------------------------
// Phase 0: reset state each launch (graph-replay safe)
// ---------------------------------------------------------------------------
__global__ void init_state(const float* __restrict__ h0) {
    int tid = threadIdx.x;
    if (tid < NCTA) g_flags[tid] = 0;
    if (tid < DIM)  g_h[0][tid] = h0[tid];
}

// ---------------------------------------------------------------------------
// Phase 1: x_proj = xs @ Wi + b   ([32768,512] @ [512,2048])
// 128x64 tile, BK=16, 256 threads, 8x4 micro-tile, fp32
// ---------------------------------------------------------------------------
__global__ __launch_bounds__(256) void gemm_xproj(
    const float* __restrict__ xs, const float* __restrict__ Wi,
    const float* __restrict__ bias)
{
    const int BM = 128, BN = 64, BK = 16;
    __shared__ float As[BK][BM];   // transposed A tile
    __shared__ float Bs[BK][BN];

    int tid = threadIdx.x;
    int tx  = tid & 15;     // n direction (x4)
    int ty  = tid >> 4;     // m direction (x8)
    int bm  = blockIdx.y * BM;
    int bn  = blockIdx.x * BN;

    float acc[8][4];
#pragma unroll
    for (int i = 0; i < 8; i++)
#pragma unroll
        for (int j = 0; j < 4; j++) acc[i][j] = 0.f;

    for (int k0 = 0; k0 < DIM; k0 += BK) {
        // A tile: 128 rows x 16 k, float4 along k, transpose into As[k][m]
#pragma unroll
        for (int it = 0; it < 2; it++) {
            int idx = tid + it * 256;          // float4 index 0..511
            int row = idx >> 2;                // 0..127
            int c4  = (idx & 3) << 2;          // 0,4,8,12
            float4 v = *(const float4*)(xs + (size_t)(bm + row) * DIM + k0 + c4);
            As[c4 + 0][row] = v.x;
            As[c4 + 1][row] = v.y;
            As[c4 + 2][row] = v.z;
            As[c4 + 3][row] = v.w;
        }
        // B tile: 16 k x 64 n, one float4 per thread
        {
            int row = tid >> 4;
            int c4  = (tid & 15) << 2;
            *(float4*)(&Bs[row][c4]) =
                *(const float4*)(Wi + (size_t)(k0 + row) * DIM4 + bn + c4);
        }
        __syncthreads();

#pragma unroll
        for (int kk = 0; kk < BK; kk++) {
            float a[8], bb[4];
            *(float4*)(a)     = *(const float4*)(&As[kk][ty * 8]);
            *(float4*)(a + 4) = *(const float4*)(&As[kk][ty * 8 + 4]);
            *(float4*)(bb)    = *(const float4*)(&Bs[kk][tx * 4]);
#pragma unroll
            for (int i = 0; i < 8; i++)
#pragma unroll
                for (int j = 0; j < 4; j++)
                    acc[i][j] = fmaf(a[i], bb[j], acc[i][j]);
        }
        __syncthreads();
    }

    float4 bv = *(const float4*)(bias + bn + tx * 4);
#pragma unroll
    for (int i = 0; i < 8; i++) {
        float4 o;
        o.x = acc[i][0] + bv.x;
        o.y = acc[i][1] + bv.y;
        o.z = acc[i][2] + bv.z;
        o.w = acc[i][3] + bv.w;
        *(float4*)(g_xp + (size_t)(bm + ty * 8 + i) * DIM4 + bn + tx * 4) = o;
    }
}

// ---------------------------------------------------------------------------
// Phase 2: persistent recurrent kernel.
// 32 CTAs x 512 threads. CTA b owns d in [16b, 16b+16). Warp w owns d=16b+w:
// all 4 gate columns (i,f,g,o) of that d, weights register-resident
// (wreg[4][16] per thread, lane l covers k = l+32m). Cross-CTA sync via
// release/acquire flags in one 128B L2 line; h double-buffered in global.
// ---------------------------------------------------------------------------
__global__ __launch_bounds__(512, 1) void lstm_rec(
    const float* __restrict__ Wh, const float* __restrict__ c0,
    float* __restrict__ out)
{
    __shared__ float hsh[DIM];
    __shared__ float xpsh[64];

    const int tid = threadIdx.x;
    const int w   = tid >> 5;      // warp 0..15 -> local d
    const int l   = tid & 31;
    const int blk = blockIdx.x;
    const int d   = blk * 16 + w;
    const int g   = l >> 3;        // lane-group -> gate (0:i 1:f 2:g 3:o)

    // Register-resident recurrent weights: wreg[q][m] = Wh[l+32m][q*512+d]
    float wreg[4][16];
#pragma unroll
    for (int q = 0; q < 4; q++)
#pragma unroll
        for (int m = 0; m < 16; m++)
            wreg[q][m] = __ldg(Wh + (size_t)(l + 32 * m) * DIM4 + q * DIM + d);

    float cst = __ldg(c0 + d);

    // Branchless activation constants: gate g==2 -> tanh, else sigmoid
    const float escale = (g == 2) ? -2.0f : -1.0f;
    const float pa     = (g == 2) ?  2.0f :  1.0f;
    const float pb     = (g == 2) ? -1.0f :  0.0f;

    const float* xp_base = g_xp + (tid >> 4) * DIM + blk * 16 + (tid & 15);
    const unsigned FULL = 0xffffffffu;

    for (int t = 0; t < L_SEQ; t++) {
        // Prefetch x_proj[t] (independent of peers) before the poll
        float xv = 0.f;
        if (tid < 64) xv = __ldg(xp_base + (size_t)t * DIM4);

        // Wait for all 32 CTAs to have published h_t
        if (tid < 32) {
            const int* fp = g_flags + tid;
            int v;
            do {
                asm volatile("ld.acquire.gpu.global.b32 %0, [%1];"
                             : "=r"(v) : "l"(fp));
            } while (v < t);
        }
        __syncthreads();

        // Stage h_t and x_proj slice into smem
        hsh[tid] = __ldcg(&g_h[t & 1][tid]);
        if (tid < 64) xpsh[tid] = xv;
        __syncthreads();

        // 64 FMAs: partial dot products for the 4 gate columns of d
        float s0 = 0.f, s1 = 0.f, s2 = 0.f, s3 = 0.f;
#pragma unroll
        for (int m = 0; m < 16; m++) {
            float hv = hsh[l + 32 * m];
            s0 = fmaf(hv, wreg[0][m], s0);
            s1 = fmaf(hv, wreg[1][m], s1);
            s2 = fmaf(hv, wreg[2][m], s2);
            s3 = fmaf(hv, wreg[3][m], s3);
        }

        // Merged butterfly reduce: 9 shfls reduce 4 values over 32 lanes;
        // ends with lane-group g holding gate-g total.
        float t0 = __shfl_xor_sync(FULL, s0, 16);
        float t2 = __shfl_xor_sync(FULL, s2, 16);
        float av = (l < 16) ? (s0 + t0) : (s2 + t2);
        float t1 = __shfl_xor_sync(FULL, s1, 16);
        float t3 = __shfl_xor_sync(FULL, s3, 16);
        float bv = (l < 16) ? (s1 + t1) : (s3 + t3);
        float a8 = __shfl_xor_sync(FULL, av, 8);
        float b8 = __shfl_xor_sync(FULL, bv, 8);
        float cc = ((l & 8) == 0) ? (av + a8) : (bv + b8);
        cc += __shfl_xor_sync(FULL, cc, 4);
        cc += __shfl_xor_sync(FULL, cc, 2);
        cc += __shfl_xor_sync(FULL, cc, 1);

        // Pre-activation + nonlinearity (per lane-group, branchless)
        float y   = cc + xpsh[g * 16 + w];
        float e   = __expf(escale * y);
        float r   = __fdividef(1.0f, 1.0f + e);
        float act = fmaf(pa, r, pb);   // sigmoid(y) or tanh(y)

        // Gather the 4 gate values to all lanes
        float vi = __shfl_sync(FULL, act, 0);
        float vf = __shfl_sync(FULL, act, 8);
        float vg = __shfl_sync(FULL, act, 16);
        float vo = __shfl_sync(FULL, act, 24);

        // State update (replicated across lanes, deterministic)
        cst = fmaf(vf, cst, vi * vg);
        float ca = fminf(fmaxf(cst, -40.f), 40.f);
        float e2 = __expf(-2.0f * ca);
        float th = fmaf(2.0f, __fdividef(1.0f, 1.0f + e2), -1.0f);
        float hn = vo * th;

        if (l == 0) {
            __stcg(&g_h[(t + 1) & 1][d], hn);
            out[(size_t)t * DIM + d] = hn;
        }
        __syncthreads();
        if (tid == 0) {
            asm volatile("st.release.gpu.global.b32 [%0], %1;"
                         :: "l"(g_flags + blk), "r"(t + 1) : "memory");
        }
    }
}

// ---------------------------------------------------------------------------
extern "C" void kernel_launch(void* const* d_in, const int* in_sizes, int n_in,
                              void* d_out, int out_size)
{
    const float* xs = (const float*)d_in[0];   // [L, 512]
    const float* Wi = (const float*)d_in[1];   // [512, 2048]
    const float* Wh = (const float*)d_in[2];   // [512, 2048]
    const float* b  = (const float*)d_in[3];   // [2048]
    const float* c0 = (const float*)d_in[4];   // [512]
    const float* h0 = (const float*)d_in[5];   // [512]
    float* out = (float*)d_out;                // [L, 512]

    init_state<<<1, 512>>>(h0);

    dim3 ggrid(DIM4 / 64, L_SEQ / 128);
    gemm_xproj<<<ggrid, 256>>>(xs, Wi, b);

    lstm_rec<<<NCTA, 512>>>(Wh, c0, out);
}

// round 4
// speedup vs baseline: 1.4561x; 1.4561x over previous
#include <cuda_runtime.h>
#include <cstdint>
#include <cstddef>

#define L_SEQ 32768
#define DIM   512
#define DIM4  2048
#define NCTA  32

// Scratch (static device globals: allocation-free per harness rules)
__device__ float g_xp[(size_t)L_SEQ * DIM4];            // 256 MB x-projection
__device__ unsigned long long g_hx[2][DIM];             // tagged hidden: (tag<<32)|bits

// ---------------------------------------------------------------------------
// Phase 0: reset state each launch (graph-replay safe).
// buf0 <- {tag=0, h0}; buf1 <- {tag=~0, 0} (never matches a wanted tag)
// ---------------------------------------------------------------------------
__global__ void init_state(const float* __restrict__ h0) {
    int tid = threadIdx.x;
    if (tid < DIM) {
        unsigned bits = __float_as_uint(h0[tid]);
        g_hx[0][tid] = (unsigned long long)bits;                       // tag 0
        g_hx[1][tid] = 0xFFFFFFFF00000000ull;                          // tag ~0
    }
}

// ---------------------------------------------------------------------------
// Phase 1: x_proj = xs @ Wi + b   ([32768,512] @ [512,2048])
// 128x64 tile, BK=16, 256 threads, 8x4 micro-tile, fp32
// ---------------------------------------------------------------------------
__global__ __launch_bounds__(256) void gemm_xproj(
    const float* __restrict__ xs, const float* __restrict__ Wi,
    const float* __restrict__ bias)
{
    const int BM = 128, BN = 64, BK = 16;
    __shared__ float As[BK][BM];   // transposed A tile
    __shared__ float Bs[BK][BN];

    int tid = threadIdx.x;
    int tx  = tid & 15;     // n direction (x4)
    int ty  = tid >> 4;     // m direction (x8)
    int bm  = blockIdx.y * BM;
    int bn  = blockIdx.x * BN;

    float acc[8][4];
#pragma unroll
    for (int i = 0; i < 8; i++)
#pragma unroll
        for (int j = 0; j < 4; j++) acc[i][j] = 0.f;

    for (int k0 = 0; k0 < DIM; k0 += BK) {
#pragma unroll
        for (int it = 0; it < 2; it++) {
            int idx = tid + it * 256;          // float4 index 0..511
            int row = idx >> 2;                // 0..127
            int c4  = (idx & 3) << 2;          // 0,4,8,12
            float4 v = *(const float4*)(xs + (size_t)(bm + row) * DIM + k0 + c4);
            As[c4 + 0][row] = v.x;
            As[c4 + 1][row] = v.y;
            As[c4 + 2][row] = v.z;
            As[c4 + 3][row] = v.w;
        }
        {
            int row = tid >> 4;
            int c4  = (tid & 15) << 2;
            *(float4*)(&Bs[row][c4]) =
                *(const float4*)(Wi + (size_t)(k0 + row) * DIM4 + bn + c4);
        }
        __syncthreads();

#pragma unroll
        for (int kk = 0; kk < BK; kk++) {
            float a[8], bb[4];
            *(float4*)(a)     = *(const float4*)(&As[kk][ty * 8]);
            *(float4*)(a + 4) = *(const float4*)(&As[kk][ty * 8 + 4]);
            *(float4*)(bb)    = *(const float4*)(&Bs[kk][tx * 4]);
#pragma unroll
            for (int i = 0; i < 8; i++)
#pragma unroll
                for (int j = 0; j < 4; j++)
                    acc[i][j] = fmaf(a[i], bb[j], acc[i][j]);
        }
        __syncthreads();
    }

    float4 bv = *(const float4*)(bias + bn + tx * 4);
#pragma unroll
    for (int i = 0; i < 8; i++) {
        float4 o;
        o.x = acc[i][0] + bv.x;
        o.y = acc[i][1] + bv.y;
        o.z = acc[i][2] + bv.z;
        o.w = acc[i][3] + bv.w;
        *(float4*)(g_xp + (size_t)(bm + ty * 8 + i) * DIM4 + bn + tx * 4) = o;
    }
}

// ---------------------------------------------------------------------------
// Phase 2: persistent recurrent kernel, tag-carried sync.
// 32 CTAs x 512 threads. Warp w of CTA b owns d=16b+w: all 4 gate columns,
// weights register-resident (wreg[4][16]/thread). Each thread polls ONE
// tagged 64-bit h element (data+tag atomic in one word -> no flags, no
// fences, single L2 hop per step). hsh/xpsh double-buffered in smem so the
// loop needs only one __syncthreads.
// ---------------------------------------------------------------------------
__global__ __launch_bounds__(512, 1) void lstm_rec(
    const float* __restrict__ Wh, const float* __restrict__ c0,
    float* __restrict__ out)
{
    __shared__ float hsh[2][DIM];
    __shared__ float xpsh[2][64];

    const int tid = threadIdx.x;
    const int w   = tid >> 5;      // warp 0..15 -> local d
    const int l   = tid & 31;
    const int blk = blockIdx.x;
    const int d   = blk * 16 + w;
    const int g   = l >> 3;        // lane-group -> gate (0:i 1:f 2:g 3:o)

    // Register-resident recurrent weights: wreg[q][m] = Wh[l+32m][q*512+d]
    float wreg[4][16];
#pragma unroll
    for (int q = 0; q < 4; q++)
#pragma unroll
        for (int m = 0; m < 16; m++)
            wreg[q][m] = __ldg(Wh + (size_t)(l + 32 * m) * DIM4 + q * DIM + d);

    float cst = __ldg(c0 + d);

    // Branchless activation constants: gate g==2 -> tanh, else sigmoid
    const float escale = (g == 2) ? -2.0f : -1.0f;
    const float pa     = (g == 2) ?  2.0f :  1.0f;
    const float pb     = (g == 2) ? -1.0f :  0.0f;

    const float* xp_base = g_xp + (tid >> 4) * DIM + blk * 16 + (tid & 15);
    const unsigned FULL = 0xffffffffu;

    for (int t = 0; t < L_SEQ; t++) {
        const int pbuf = t & 1;

        // Prefetch x_proj[t] (independent of peers) before the poll
        float xv = 0.f;
        if (tid < 64) xv = __ldcs(xp_base + (size_t)t * DIM4);

        // Poll own tagged h element until tag == t (L1-bypassing GPU-scope ld)
        {
            const unsigned long long* hp = &g_hx[pbuf][tid];
            const unsigned want = (unsigned)t;
            unsigned long long v;
            do {
                asm volatile("ld.relaxed.gpu.global.b64 %0, [%1];"
                             : "=l"(v) : "l"(hp));
            } while ((unsigned)(v >> 32) != want);
            hsh[pbuf][tid] = __uint_as_float((unsigned)v);
        }
        if (tid < 64) xpsh[pbuf][tid] = xv;
        __syncthreads();

        // 64 FMAs: partial dot products for the 4 gate columns of d
        float s0 = 0.f, s1 = 0.f, s2 = 0.f, s3 = 0.f;
#pragma unroll
        for (int m = 0; m < 16; m++) {
            float hv = hsh[pbuf][l + 32 * m];
            s0 = fmaf(hv, wreg[0][m], s0);
            s1 = fmaf(hv, wreg[1][m], s1);
            s2 = fmaf(hv, wreg[2][m], s2);
            s3 = fmaf(hv, wreg[3][m], s3);
        }

        // Merged butterfly reduce: 4 sums over 32 lanes in ~9 shfls;
        // ends with lane-group g holding gate-g total.
        float t0 = __shfl_xor_sync(FULL, s0, 16);
        float t2 = __shfl_xor_sync(FULL, s2, 16);
        float av = (l < 16) ? (s0 + t0) : (s2 + t2);
        float t1 = __shfl_xor_sync(FULL, s1, 16);
        float t3 = __shfl_xor_sync(FULL, s3, 16);
        float bv = (l < 16) ? (s1 + t1) : (s3 + t3);
        float a8 = __shfl_xor_sync(FULL, av, 8);
        float b8 = __shfl_xor_sync(FULL, bv, 8);
        float cc = ((l & 8) == 0) ? (av + a8) : (bv + b8);
        cc += __shfl_xor_sync(FULL, cc, 4);
        cc += __shfl_xor_sync(FULL, cc, 2);
        cc += __shfl_xor_sync(FULL, cc, 1);

        // Pre-activation + nonlinearity (per lane-group, branchless)
        float y   = cc + xpsh[pbuf][g * 16 + w];
        float e   = __expf(escale * y);
        float r   = __fdividef(1.0f, 1.0f + e);
        float act = fmaf(pa, r, pb);   // sigmoid(y) or tanh(y)

        // Gather the 4 gate values to all lanes
        float vi = __shfl_sync(FULL, act, 0);
        float vf = __shfl_sync(FULL, act, 8);
        float vg = __shfl_sync(FULL, act, 16);
        float vo = __shfl_sync(FULL, act, 24);

        // State update (replicated across lanes, deterministic)
        cst = fmaf(vf, cst, vi * vg);
        float ca = fminf(fmaxf(cst, -40.f), 40.f);
        float e2 = __expf(-2.0f * ca);
        float th = fmaf(2.0f, __fdividef(1.0f, 1.0f + e2), -1.0f);
        float hn = vo * th;

        // Publish h_{t+1} with tag t+1 (single atomic 64-bit word)
        if (l == 0) {
            unsigned long long pk =
                ((unsigned long long)(unsigned)(t + 1) << 32) |
                (unsigned long long)__float_as_uint(hn);
            asm volatile("st.relaxed.gpu.global.b64 [%0], %1;"
                         :: "l"(&g_hx[(t + 1) & 1][d]), "l"(pk) : "memory");
        } else if (l == 1) {
            __stcs(out + (size_t)t * DIM + d, hn);
        }
        // no second barrier: hsh/xpsh are double-buffered
    }
}

// ---------------------------------------------------------------------------
extern "C" void kernel_launch(void* const* d_in, const int* in_sizes, int n_in,
                              void* d_out, int out_size)
{
    const float* xs = (const float*)d_in[0];   // [L, 512]
    const float* Wi = (const float*)d_in[1];   // [512, 2048]
    const float* Wh = (const float*)d_in[2];   // [512, 2048]
    const float* b  = (const float*)d_in[3];   // [2048]
    const float* c0 = (const float*)d_in[4];   // [512]
    const float* h0 = (const float*)d_in[5];   // [512]
    float* out = (float*)d_out;                // [L, 512]

    init_state<<<1, 512>>>(h0);

    dim3 ggrid(DIM4 / 64, L_SEQ / 128);
    gemm_xproj<<<ggrid, 256>>>(xs, Wi, b);

    lstm_rec<<<NCTA, 512>>>(Wh, c0, out);
}

// round 7
// speedup vs baseline: 1.6114x; 1.1066x over previous
#include <cuda_runtime.h>
#include <cstdint>
#include <cstddef>

#define L_SEQ 32768
#define DIM   512
#define DIM4  2048
#define NCTA  32          // recurrence CTAs
#define GCTA  116         // GEMM CTAs (total grid = 148)
#define NBLK  256         // row-blocks of 128 rows
#define NTIL  4096        // 256 row-blocks x 16 col-tiles

// Scratch (static device globals: allocation-free per harness rules)
__device__ float g_xp[(size_t)L_SEQ * DIM4];      // 256 MB x-projection
__device__ unsigned long long g_hx[2][DIM];       // tagged hidden: (tag<<32)|bits
__device__ int g_cnt[NBLK];                       // per-row-block completed tiles

// ---------------------------------------------------------------------------
// Phase 0: reset state each launch (graph-replay safe)
// ---------------------------------------------------------------------------
__global__ void init_state(const float* __restrict__ h0) {
    int tid = threadIdx.x;
    if (tid < NBLK) g_cnt[tid] = 0;
    if (tid < DIM) {
        g_hx[0][tid] = (unsigned long long)__float_as_uint(h0[tid]);  // tag 0
        g_hx[1][tid] = 0xFFFFFFFF00000000ull;                         // tag ~0
    }
}

struct GemmSmem { float As[16][132]; float Bs[16][128]; };   // 16.6 KB
struct RecSmem  { float hsh[2][DIM]; float xpsh[2][64]; };   //  4.6 KB

// ---------------------------------------------------------------------------
// Fused kernel: CTAs 0..31 run the sequential LSTM; CTAs 32..147 run the
// x-projection GEMM persistently, publishing row-block readiness via g_cnt.
// GEMM stays ~6x ahead of the recurrence's consumption rate, so its entire
// cost hides under the recurrence.
// ---------------------------------------------------------------------------
__global__ __launch_bounds__(512, 1) void lstm_fused(
    const float* __restrict__ xs, const float* __restrict__ Wi,
    const float* __restrict__ bias, const float* __restrict__ Wh,
    const float* __restrict__ c0, float* __restrict__ out)
{
    __shared__ __align__(16) unsigned char s_raw[sizeof(GemmSmem)];
    const int tid = threadIdx.x;
    const int blk = blockIdx.x;

    // =================== GEMM path (CTAs 32..147) ===================
    if (blk >= NCTA) {
        GemmSmem& S = *reinterpret_cast<GemmSmem*>(s_raw);
        const int tx = tid & 31;   // n: 4 cols each
        const int ty = tid >> 5;   // m: 8 rows each

        for (int idx = blk - NCTA; idx < NTIL; idx += GCTA) {
            const int bm = (idx >> 4) * 128;   // row-major tile order
            const int bn = (idx & 15) * 128;

            float acc[8][4];
#pragma unroll
            for (int i = 0; i < 8; i++)
#pragma unroll
                for (int j = 0; j < 4; j++) acc[i][j] = 0.f;

            for (int k0 = 0; k0 < DIM; k0 += 16) {
                {   // A tile 128x16, transposed into As[k][m]
                    int row = tid >> 2;
                    int c4  = (tid & 3) << 2;
                    float4 v = *(const float4*)(xs + (size_t)(bm + row) * DIM + k0 + c4);
                    S.As[c4 + 0][row] = v.x;
                    S.As[c4 + 1][row] = v.y;
                    S.As[c4 + 2][row] = v.z;
                    S.As[c4 + 3][row] = v.w;
                }
                {   // B tile 16x128
                    int row = tid >> 5;
                    int c4  = (tid & 31) << 2;
                    *(float4*)(&S.Bs[row][c4]) =
                        *(const float4*)(Wi + (size_t)(k0 + row) * DIM4 + bn + c4);
                }
                __syncthreads();
#pragma unroll
                for (int kk = 0; kk < 16; kk++) {
                    float a[8], bb[4];
                    *(float4*)(a)     = *(const float4*)(&S.As[kk][ty * 8]);     // bcast
                    *(float4*)(a + 4) = *(const float4*)(&S.As[kk][ty * 8 + 4]);
                    *(float4*)(bb)    = *(const float4*)(&S.Bs[kk][tx * 4]);
#pragma unroll
                    for (int i = 0; i < 8; i++)
#pragma unroll
                        for (int j = 0; j < 4; j++)
                            acc[i][j] = fmaf(a[i], bb[j], acc[i][j]);
                }
                __syncthreads();
            }

            float4 bv = *(const float4*)(bias + bn + tx * 4);
#pragma unroll
            for (int i = 0; i < 8; i++) {
                float4 o;
                o.x = acc[i][0] + bv.x;
                o.y = acc[i][1] + bv.y;
                o.z = acc[i][2] + bv.z;
                o.w = acc[i][3] + bv.w;
                *(float4*)(g_xp + (size_t)(bm + ty * 8 + i) * DIM4 + bn + tx * 4) = o;
            }
            __threadfence();           // each thread fences its own stores
            __syncthreads();
            if (tid == 0) atomicAdd(&g_cnt[idx >> 4], 1);
        }
        return;
    }

    // =================== Recurrence path (CTAs 0..31) ===================
    RecSmem& R = *reinterpret_cast<RecSmem*>(s_raw);
    const int w = tid >> 5;        // warp 0..15 -> local d
    const int l = tid & 31;
    const int d = blk * 16 + w;
    const int g = l >> 3;          // lane-group -> gate (0:i 1:f 2:g 3:o)

    // Register-resident weights: lane l covers k = 2l + 64m + j (m<8, j<2)
    float wreg[4][8][2];
#pragma unroll
    for (int q = 0; q < 4; q++)
#pragma unroll
        for (int m = 0; m < 8; m++)
#pragma unroll
            for (int j = 0; j < 2; j++)
                wreg[q][m][j] = __ldg(Wh + (size_t)(2 * l + 64 * m + j) * DIM4 + q * DIM + d);

    float cst = __ldg(c0 + d);

    const float escale = (g == 2) ? -2.0f : -1.0f;
    const float pa     = (g == 2) ?  2.0f :  1.0f;
    const float pb     = (g == 2) ? -1.0f :  0.0f;

    const float* xp_base = g_xp + (tid >> 4) * DIM + blk * 16 + (tid & 15);
    const unsigned FULL = 0xffffffffu;

    int rdy = 0;   // row-blocks confirmed complete (tid0 only)
    if (tid == 0) {
        while (rdy < 1) {
            int c;
            asm volatile("ld.acquire.gpu.global.b32 %0, [%1];"
                         : "=r"(c) : "l"(g_cnt + rdy));
            if (c == 16) rdy++;
        }
    }
    __syncthreads();

    // xv is prefetched ONE STEP AHEAD: issued during step t-1's compute window
    float xv = (tid < 64) ? __ldcs(xp_base) : 0.f;

    for (int t = 0; t < L_SEQ; t++) {
        const int pbuf = t & 1;

        // Poll own tagged h element until tag == t
        {
            const unsigned long long* hp = &g_hx[pbuf][tid];
            const unsigned want = (unsigned)t;
            unsigned long long v;
            do {
                asm volatile("ld.relaxed.gpu.global.b64 %0, [%1];"
                             : "=l"(v) : "l"(hp));
            } while ((unsigned)(v >> 32) != want);
            R.hsh[pbuf][tid] = __uint_as_float((unsigned)v);
        }
        // tid0: guarantee row-block of step t+1 is GEMM-complete (rare wait)
        if (tid == 0) {
            int need = ((t + 1) >> 7) + 1;
            if (need > NBLK) need = NBLK;
            while (rdy < need) {
                int c;
                asm volatile("ld.acquire.gpu.global.b32 %0, [%1];"
                             : "=r"(c) : "l"(g_cnt + rdy));
                if (c == 16) rdy++;
            }
        }
        if (tid < 64) R.xpsh[pbuf][tid] = xv;
        __syncthreads();

        // Prefetch x_proj[t+1] now — fully covered by compute + next sync
        if (tid < 64 && t + 1 < L_SEQ)
            xv = __ldcs(xp_base + (size_t)(t + 1) * DIM4);

        // 64 FMAs via 8 float2 LDS (conflict-free)
        float s0 = 0.f, s1 = 0.f, s2 = 0.f, s3 = 0.f;
#pragma unroll
        for (int m = 0; m < 8; m++) {
            float2 hv = *(const float2*)(&R.hsh[pbuf][2 * l + 64 * m]);
            s0 = fmaf(hv.x, wreg[0][m][0], fmaf(hv.y, wreg[0][m][1], s0));
            s1 = fmaf(hv.x, wreg[1][m][0], fmaf(hv.y, wreg[1][m][1], s1));
            s2 = fmaf(hv.x, wreg[2][m][0], fmaf(hv.y, wreg[2][m][1], s2));
            s3 = fmaf(hv.x, wreg[3][m][0], fmaf(hv.y, wreg[3][m][1], s3));
        }

        // Merged butterfly reduce: 4 sums over 32 lanes, ~9 shfls;
        // lane-group g ends holding gate-g total.
        float t0 = __shfl_xor_sync(FULL, s0, 16);
        float t2 = __shfl_xor_sync(FULL, s2, 16);
        float av = (l < 16) ? (s0 + t0) : (s2 + t2);
        float t1 = __shfl_xor_sync(FULL, s1, 16);
        float t3 = __shfl_xor_sync(FULL, s3, 16);
        float bv = (l < 16) ? (s1 + t1) : (s3 + t3);
        float a8 = __shfl_xor_sync(FULL, av, 8);
        float b8 = __shfl_xor_sync(FULL, bv, 8);
        float cc = ((l & 8) == 0) ? (av + a8) : (bv + b8);
        cc += __shfl_xor_sync(FULL, cc, 4);
        cc += __shfl_xor_sync(FULL, cc, 2);
        cc += __shfl_xor_sync(FULL, cc, 1);

        // Activation (branchless per lane-group)
        float y   = cc + R.xpsh[pbuf][g * 16 + w];
        float e   = __expf(escale * y);
        float r   = __fdividef(1.0f, 1.0f + e);
        float act = fmaf(pa, r, pb);   // sigmoid(y) or tanh(y)

        float vi = __shfl_sync(FULL, act, 0);
        float vf = __shfl_sync(FULL, act, 8);
        float vg = __shfl_sync(FULL, act, 16);
        float vo = __shfl_sync(FULL, act, 24);

        cst = fmaf(vf, cst, vi * vg);
        float ca = fminf(fmaxf(cst, -40.f), 40.f);
        float e2 = __expf(-2.0f * ca);
        float th = fmaf(2.0f, __fdividef(1.0f, 1.0f + e2), -1.0f);
        float hn = vo * th;

        if (l == 0) {
            unsigned long long pk =
                ((unsigned long long)(unsigned)(t + 1) << 32) |
                (unsigned long long)__float_as_uint(hn);
            asm volatile("st.relaxed.gpu.global.b64 [%0], %1;"
                         :: "l"(&g_hx[(t + 1) & 1][d]), "l"(pk) : "memory");
        } else if (l == 1) {
            __stcs(out + (size_t)t * DIM + d, hn);
        }
        // no trailing barrier: hsh/xpsh double-buffered
    }
}

// ---------------------------------------------------------------------------
extern "C" void kernel_launch(void* const* d_in, const int* in_sizes, int n_in,
                              void* d_out, int out_size)
{
    const float* xs = (const float*)d_in[0];   // [L, 512]
    const float* Wi = (const float*)d_in[1];   // [512, 2048]
    const float* Wh = (const float*)d_in[2];   // [512, 2048]
    const float* b  = (const float*)d_in[3];   // [2048]
    const float* c0 = (const float*)d_in[4];   // [512]
    const float* h0 = (const float*)d_in[5];   // [512]
    float* out = (float*)d_out;                // [L, 512]

    init_state<<<1, 512>>>(h0);
    lstm_fused<<<NCTA + GCTA, 512>>>(xs, Wi, b, Wh, c0, out);
}